// round 14
// baseline (speedup 1.0000x reference)
#include <cuda_runtime.h>

#define NN   4096
#define INF  256
#define HH   128
#define NW   128      // mask words per row
#define KSJ  2048     // j-range per K-split (split = 2)
#define NMB  (NN * NN / 256)   // maskbuild blocks

// ---------------- scratch (device globals) -----------------------------------
__device__ float    g_W1h[NN * HH];
__device__ float    g_W2h[NN * HH];
__device__ float    g_s1[NN];
__device__ float    g_s2[NN];
__device__ unsigned g_M1[NN * NW];
__device__ unsigned g_M2[NN * NW];
__device__ unsigned g_M3[NN * NW];
__device__ float    g_hk0[NN * HH];     // per-hop h_k (sparse hops)
__device__ float    g_hk1[NN * HH];
__device__ float    g_hk2[NN * HH];     // dense hop h_k (combined)
__device__ float    g_O0[NN * HH];      // per-hop outputs (sparse hops)
__device__ float    g_O1[NN * HH];
__device__ float    g_hp[2 * NN * HH];  // dense split-K partials
__device__ float    g_zp[2 * NN];

// ---------------- tf32 helpers -----------------------------------------------
__device__ __forceinline__ float tfr(float f) {
    unsigned u;
    asm("cvt.rna.tf32.f32 %0, %1;" : "=r"(u) : "f"(f));
    return __uint_as_float(u);
}
__device__ __forceinline__ void mma_tf32(float* c, const unsigned* a, const unsigned* b) {
    asm("mma.sync.aligned.m16n8k8.row.col.f32.tf32.tf32.f32 "
        "{%0,%1,%2,%3},{%4,%5,%6,%7},{%8,%9},{%0,%1,%2,%3};"
        : "+f"(c[0]), "+f"(c[1]), "+f"(c[2]), "+f"(c[3])
        : "r"(a[0]), "r"(a[1]), "r"(a[2]), "r"(a[3]), "r"(b[0]), "r"(b[1]));
}

// ---------------- K1: W1h = X@W1^T, W2h = X@W2^T -----------------------------
__global__ void prep_kernel(const float* __restrict__ X,
                            const float* __restrict__ W1,
                            const float* __restrict__ W2) {
    __shared__ float xs[32][INF];
    const int t    = threadIdx.x;
    const int row0 = blockIdx.x * 32;

    const float4* Xv  = reinterpret_cast<const float4*>(X + (size_t)row0 * INF);
    float4*       xsv = reinterpret_cast<float4*>(&xs[0][0]);
    for (int k = t; k < 32 * INF / 4; k += 256) xsv[k] = Xv[k];
    __syncthreads();

    const float* W = (t < HH) ? (W1 + (size_t)t * INF)
                              : (W2 + (size_t)(t - HH) * INF);
    float acc[32];
#pragma unroll
    for (int rr = 0; rr < 32; rr++) acc[rr] = 0.f;

    for (int c = 0; c < INF; c += 4) {
        float4 w4 = *reinterpret_cast<const float4*>(W + c);
#pragma unroll
        for (int rr = 0; rr < 32; rr++) {
            float4 x4 = *reinterpret_cast<const float4*>(&xs[rr][c]);
            acc[rr] += x4.x * w4.x + x4.y * w4.y + x4.z * w4.z + x4.w * w4.w;
        }
    }
#pragma unroll
    for (int rr = 0; rr < 32; rr++) {
        const int row = row0 + rr;
        if (t < HH) g_W1h[(size_t)row * HH + t] = acc[rr];
        else        g_W2h[(size_t)row * HH + (t - HH)] = acc[rr];
    }
}

// ---------------- K2a: s12 ----------------------------------------------------
__global__ void s12_kernel(const float* __restrict__ r) {
    const int i = blockIdx.x, t = threadIdx.x;
    const float w  = g_W1h[(size_t)i * HH + t];
    float v1 = w * r[t];
    float v2 = w * r[HH + t];
#pragma unroll
    for (int o = 16; o; o >>= 1) {
        v1 += __shfl_xor_sync(0xFFFFFFFFu, v1, o);
        v2 += __shfl_xor_sync(0xFFFFFFFFu, v2, o);
    }
    __shared__ float sh1[4], sh2[4];
    if ((t & 31) == 0) { sh1[t >> 5] = v1; sh2[t >> 5] = v2; }
    __syncthreads();
    if (t == 0) g_s1[i] = sh1[0] + sh1[1] + sh1[2] + sh1[3];
    if (t == 1) g_s2[i] = sh2[0] + sh2[1] + sh2[2] + sh2[3];
}

// ---------------- K2b: bitmask of A ------------------------------------------
__global__ void maskbuild_kernel(const float* __restrict__ A) {
    const int gid = blockIdx.x * 256 + threadIdx.x;
    const float a = A[gid];
    const unsigned b = __ballot_sync(0xFFFFFFFFu, a != 0.0f);
    if ((threadIdx.x & 31) == 0) g_M1[gid >> 5] = b;
}

// ---------------- K3: boolean mat-power --------------------------------------
__global__ void boolmm_kernel(int mode) {
    const unsigned* Min  = (mode == 0) ? g_M1 : g_M2;
    unsigned*       Mout = (mode == 0) ? g_M2 : g_M3;
    const int i = blockIdx.x, t = threadIdx.x;
    __shared__ unsigned sh[NW];
    sh[t] = g_M1[(size_t)i * NW + t];
    __syncthreads();
    unsigned acc = 0;
    for (int w = 0; w < NW; w++) {
        unsigned bits = sh[w];
        while (bits) {
            const int b = __ffs(bits) - 1;
            bits &= bits - 1;
            acc |= Min[(size_t)(w * 32 + b) * NW + t];
        }
    }
    Mout[(size_t)i * NW + t] = acc;
}

// ================= SPARSE kernels (hops 0,1) =================================
__global__ __launch_bounds__(256) void sattn1_kernel(int hop) {
    const unsigned* M = (hop == 0) ? g_M1 : g_M2;
    float* hkout      = (hop == 0) ? g_hk0 : g_hk1;
    const int i = blockIdx.x;
    __shared__ unsigned short idxs[NN];
    __shared__ float plist[NN];
    __shared__ int   wsum[4];
    __shared__ float comb[HH + 4];

    const int t = threadIdx.x, l = t & 31, w = t >> 5;
    int c = 0, sc = 0; unsigned word = 0;
    if (t < 128) {
        word = M[(size_t)i * NW + t];
        c = __popc(word); sc = c;
#pragma unroll
        for (int o = 1; o < 32; o <<= 1) {
            int v = __shfl_up_sync(0xFFFFFFFFu, sc, o);
            if (l >= o) sc += v;
        }
        if (l == 31) wsum[w] = sc;
    }
    __syncthreads();
    const int n = wsum[0] + wsum[1] + wsum[2] + wsum[3];
    if (t < 128) {
        int base = 0;
#pragma unroll
        for (int q = 0; q < 4; q++) if (q < w) base += wsum[q];
        int off = base + sc - c;
        const float s1i = g_s1[i];
        unsigned b = word;
        while (b) {
            const int bit = __ffs(b) - 1;
            b &= b - 1;
            const int j = t * 32 + bit;
            const float e  = s1i + g_s2[j];
            const float lr = fmaxf(e, 0.2f * e);
            idxs[off]  = (unsigned short)j;
            plist[off] = __expf(lr - 40.0f);
            off++;
        }
    }
    __syncthreads();

    const int h = t >> 7, tl = t & 127;
    int nh = ((n >> 1) + 3) & ~3; if (nh > n) nh = n;
    const int k0 = h ? nh : 0, k1 = h ? n : nh;
    float a0 = 0.f, a1 = 0.f, a2 = 0.f, a3 = 0.f;
    float z0 = 0.f, z1 = 0.f, z2 = 0.f, z3 = 0.f;
    int k = k0;
    for (; k + 4 <= k1; k += 4) {
        const float p0 = plist[k], p1 = plist[k+1], p2 = plist[k+2], p3 = plist[k+3];
        const int j0 = idxs[k], j1 = idxs[k+1], j2 = idxs[k+2], j3 = idxs[k+3];
        a0 = fmaf(p0, g_W1h[(size_t)j0 * HH + tl], a0); z0 += p0;
        a1 = fmaf(p1, g_W1h[(size_t)j1 * HH + tl], a1); z1 += p1;
        a2 = fmaf(p2, g_W1h[(size_t)j2 * HH + tl], a2); z2 += p2;
        a3 = fmaf(p3, g_W1h[(size_t)j3 * HH + tl], a3); z3 += p3;
    }
    for (; k < k1; k++) {
        const float p = plist[k];
        a0 = fmaf(p, g_W1h[(size_t)idxs[k] * HH + tl], a0); z0 += p;
    }
    const float acc = (a0 + a1) + (a2 + a3);
    const float z   = (z0 + z1) + (z2 + z3);
    if (h == 1) { comb[tl] = acc; if (tl == 0) comb[HH] = z; }
    __syncthreads();
    if (h == 0)
        hkout[(size_t)i * HH + tl] = (acc + comb[tl]) / (z + comb[HH]);
}

__global__ __launch_bounds__(256) void sattn2_kernel(int hop) {
    const unsigned* M  = (hop == 0) ? g_M1 : g_M2;
    const float* hkin  = (hop == 0) ? g_hk0 : g_hk1;
    float* Oout        = (hop == 0) ? g_O0 : g_O1;
    const int i = blockIdx.x;
    __shared__ unsigned short idxs[NN];
    __shared__ float plist[NN];
    __shared__ int   wsum[4];
    __shared__ float comb[HH + 4];

    const int t = threadIdx.x, l = t & 31, w = t >> 5;
    const float hv0 = hkin[(size_t)i * HH + l];
    const float hv1 = hkin[(size_t)i * HH + l + 32];
    const float hv2 = hkin[(size_t)i * HH + l + 64];
    const float hv3 = hkin[(size_t)i * HH + l + 96];

    int c = 0, sc = 0; unsigned word = 0;
    if (t < 128) {
        word = M[(size_t)i * NW + t];
        c = __popc(word); sc = c;
#pragma unroll
        for (int o = 1; o < 32; o <<= 1) {
            int v = __shfl_up_sync(0xFFFFFFFFu, sc, o);
            if (l >= o) sc += v;
        }
        if (l == 31) wsum[w] = sc;
    }
    __syncthreads();
    const int n = wsum[0] + wsum[1] + wsum[2] + wsum[3];
    if (t < 128) {
        int base = 0;
#pragma unroll
        for (int q = 0; q < 4; q++) if (q < w) base += wsum[q];
        int off = base + sc - c;
        unsigned b = word;
        while (b) {
            const int bit = __ffs(b) - 1;
            b &= b - 1;
            idxs[off++] = (unsigned short)(t * 32 + bit);
        }
    }
    __syncthreads();

    int k = w;
    for (; k + 8 < n; k += 16) {
        const int ja = idxs[k], jb = idxs[k + 8];
        const float* Wa = g_W2h + (size_t)ja * HH;
        const float* Wb = g_W2h + (size_t)jb * HH;
        float da = hv0 * Wa[l] + hv1 * Wa[l+32] + hv2 * Wa[l+64] + hv3 * Wa[l+96];
        float db = hv0 * Wb[l] + hv1 * Wb[l+32] + hv2 * Wb[l+64] + hv3 * Wb[l+96];
#pragma unroll
        for (int o = 16; o; o >>= 1) {
            da += __shfl_xor_sync(0xFFFFFFFFu, da, o);
            db += __shfl_xor_sync(0xFFFFFFFFu, db, o);
        }
        if (l == 0) { plist[k] = __expf(da); plist[k + 8] = __expf(db); }
    }
    for (; k < n; k += 8) {
        const int j = idxs[k];
        const float* W = g_W2h + (size_t)j * HH;
        float d = hv0 * W[l] + hv1 * W[l+32] + hv2 * W[l+64] + hv3 * W[l+96];
#pragma unroll
        for (int o = 16; o; o >>= 1) d += __shfl_xor_sync(0xFFFFFFFFu, d, o);
        if (l == 0) plist[k] = __expf(d);
    }
    __syncthreads();

    const int h = t >> 7, tl = t & 127;
    int nh = ((n >> 1) + 3) & ~3; if (nh > n) nh = n;
    const int k0 = h ? nh : 0, k1 = h ? n : nh;
    float a0 = 0.f, a1 = 0.f, a2 = 0.f, a3 = 0.f;
    float z0 = 0.f, z1 = 0.f, z2 = 0.f, z3 = 0.f;
    k = k0;
    for (; k + 4 <= k1; k += 4) {
        const float p0 = plist[k], p1 = plist[k+1], p2 = plist[k+2], p3 = plist[k+3];
        const int j0 = idxs[k], j1 = idxs[k+1], j2 = idxs[k+2], j3 = idxs[k+3];
        a0 = fmaf(p0, hkin[(size_t)j0 * HH + tl], a0); z0 += p0;
        a1 = fmaf(p1, hkin[(size_t)j1 * HH + tl], a1); z1 += p1;
        a2 = fmaf(p2, hkin[(size_t)j2 * HH + tl], a2); z2 += p2;
        a3 = fmaf(p3, hkin[(size_t)j3 * HH + tl], a3); z3 += p3;
    }
    for (; k < k1; k++) {
        const float p = plist[k];
        a0 = fmaf(p, hkin[(size_t)idxs[k] * HH + tl], a0); z0 += p;
    }
    const float acc = (a0 + a1) + (a2 + a3);
    const float z   = (z0 + z1) + (z2 + z3);
    if (h == 1) { comb[tl] = acc; if (tl == 0) comb[HH] = z; }
    __syncthreads();
    if (h == 0)
        Oout[(size_t)i * HH + tl] = (acc + comb[tl]) / (z + comb[HH]);
}

// ================= DENSE tf32 tensor-core kernels (hop 2) ====================
// dattn1: register-double-buffered V-tile loads.
__global__ __launch_bounds__(256, 2) void dattn1_tc() {
    __shared__ float s2s[NN];
    __shared__ float Vt[32][136];
    const int t = threadIdx.x, warp = t >> 5, lane = t & 31;
    const int gid = lane >> 2, tig = lane & 3;
    const int wm = warp >> 2, wn = warp & 3;
    const int i0 = blockIdx.x * 32;
    const int jlo = blockIdx.y * KSJ;
    const int r1 = wm * 16 + gid, r2 = r1 + 8;
    const int lrr0 = (t) >> 5,          lcc0 = ((t) & 31) << 2;
    const int lrr1 = (t + 256) >> 5,    lcc1 = ((t + 256) & 31) << 2;
    const int lrr2 = (t + 512) >> 5,    lcc2 = ((t + 512) & 31) << 2;
    const int lrr3 = (t + 768) >> 5,    lcc3 = ((t + 768) & 31) << 2;

    for (int k = t; k < NN / 4; k += 256)
        reinterpret_cast<float4*>(s2s)[k] = reinterpret_cast<const float4*>(g_s2)[k];

    const float s1a = g_s1[i0 + r1];
    const float s1b = g_s1[i0 + r2];

    float cacc[4][4];
#pragma unroll
    for (int nf = 0; nf < 4; nf++)
#pragma unroll
        for (int q = 0; q < 4; q++) cacc[nf][q] = 0.f;
    float zr1 = 0.f, zr2 = 0.f;

    float4 rv0 = *reinterpret_cast<const float4*>(g_W1h + (size_t)(jlo + lrr0) * HH + lcc0);
    float4 rv1 = *reinterpret_cast<const float4*>(g_W1h + (size_t)(jlo + lrr1) * HH + lcc1);
    float4 rv2 = *reinterpret_cast<const float4*>(g_W1h + (size_t)(jlo + lrr2) * HH + lcc2);
    float4 rv3 = *reinterpret_cast<const float4*>(g_W1h + (size_t)(jlo + lrr3) * HH + lcc3);
    __syncthreads();

    for (int j0 = jlo; j0 < jlo + KSJ; j0 += 32) {
        float4 v;
        v = rv0; v.x=tfr(v.x); v.y=tfr(v.y); v.z=tfr(v.z); v.w=tfr(v.w);
        *reinterpret_cast<float4*>(&Vt[lrr0][lcc0]) = v;
        v = rv1; v.x=tfr(v.x); v.y=tfr(v.y); v.z=tfr(v.z); v.w=tfr(v.w);
        *reinterpret_cast<float4*>(&Vt[lrr1][lcc1]) = v;
        v = rv2; v.x=tfr(v.x); v.y=tfr(v.y); v.z=tfr(v.z); v.w=tfr(v.w);
        *reinterpret_cast<float4*>(&Vt[lrr2][lcc2]) = v;
        v = rv3; v.x=tfr(v.x); v.y=tfr(v.y); v.z=tfr(v.z); v.w=tfr(v.w);
        *reinterpret_cast<float4*>(&Vt[lrr3][lcc3]) = v;
        __syncthreads();

        if (j0 + 32 < jlo + KSJ) {
            rv0 = *reinterpret_cast<const float4*>(g_W1h + (size_t)(j0 + 32 + lrr0) * HH + lcc0);
            rv1 = *reinterpret_cast<const float4*>(g_W1h + (size_t)(j0 + 32 + lrr1) * HH + lcc1);
            rv2 = *reinterpret_cast<const float4*>(g_W1h + (size_t)(j0 + 32 + lrr2) * HH + lcc2);
            rv3 = *reinterpret_cast<const float4*>(g_W1h + (size_t)(j0 + 32 + lrr3) * HH + lcc3);
        }

        const unsigned wd1 = g_M3[(size_t)(i0 + r1) * NW + (j0 >> 5)];
        const unsigned wd2 = g_M3[(size_t)(i0 + r2) * NW + (j0 >> 5)];
#pragma unroll
        for (int kss = 0; kss < 4; kss++) {
            const int cA = kss * 8 + tig, cB = cA + 4;
            const float s2A = s2s[j0 + cA], s2B = s2s[j0 + cB];
            const float eA1 = s1a + s2A, eA2 = s1b + s2A;
            const float eB1 = s1a + s2B, eB2 = s1b + s2B;
            float p0 = ((wd1 >> cA) & 1u) ? __expf(fmaxf(eA1, 0.2f * eA1) - 40.f) : 0.f;
            float p1 = ((wd2 >> cA) & 1u) ? __expf(fmaxf(eA2, 0.2f * eA2) - 40.f) : 0.f;
            float p2 = ((wd1 >> cB) & 1u) ? __expf(fmaxf(eB1, 0.2f * eB1) - 40.f) : 0.f;
            float p3 = ((wd2 >> cB) & 1u) ? __expf(fmaxf(eB2, 0.2f * eB2) - 40.f) : 0.f;
            p0 = tfr(p0); p1 = tfr(p1); p2 = tfr(p2); p3 = tfr(p3);
            if (wn == 0) { zr1 += p0 + p2; zr2 += p1 + p3; }
            unsigned a[4] = { __float_as_uint(p0), __float_as_uint(p1),
                              __float_as_uint(p2), __float_as_uint(p3) };
#pragma unroll
            for (int nf = 0; nf < 4; nf++) {
                const int ch = wn * 32 + nf * 8 + gid;
                unsigned b[2] = { __float_as_uint(Vt[cA][ch]),
                                  __float_as_uint(Vt[cB][ch]) };
                mma_tf32(cacc[nf], a, b);
            }
        }
        __syncthreads();
    }

    if (wn == 0) {
        zr1 += __shfl_xor_sync(0xFFFFFFFFu, zr1, 1);
        zr1 += __shfl_xor_sync(0xFFFFFFFFu, zr1, 2);
        zr2 += __shfl_xor_sync(0xFFFFFFFFu, zr2, 1);
        zr2 += __shfl_xor_sync(0xFFFFFFFFu, zr2, 2);
        if (tig == 0) {
            g_zp[blockIdx.y * NN + i0 + r1] = zr1;
            g_zp[blockIdx.y * NN + i0 + r2] = zr2;
        }
    }
    float* P = g_hp + (size_t)blockIdx.y * NN * HH;
#pragma unroll
    for (int nf = 0; nf < 4; nf++) {
        const int ch = wn * 32 + nf * 8 + 2 * tig;
        P[(size_t)(i0 + r1) * HH + ch]     = cacc[nf][0];
        P[(size_t)(i0 + r1) * HH + ch + 1] = cacc[nf][1];
        P[(size_t)(i0 + r2) * HH + ch]     = cacc[nf][2];
        P[(size_t)(i0 + r2) * HH + ch + 1] = cacc[nf][3];
    }
}

__global__ void combine1_kernel() {
    const int i = blockIdx.x, t = threadIdx.x;
    const size_t ix = (size_t)i * HH + t;
    const float z = g_zp[i] + g_zp[NN + i];
    g_hk2[ix] = (g_hp[ix] + g_hp[(size_t)NN * HH + ix]) / z;
}

// attn2: hq A-fragments hoisted into registers; separate W2h / hk tile buffers.
__global__ __launch_bounds__(256, 2) void dattn2_tc() {
    __shared__ float BtW[32][136];
    __shared__ float Bth[32][136];
    __shared__ float Pst[32][40];
    __shared__ float Zp[4][32];
    const int t = threadIdx.x, warp = t >> 5, lane = t & 31;
    const int gid = lane >> 2, tig = lane & 3;
    const int wm = warp >> 2, wn = warp & 3;
    const int i0 = blockIdx.x * 32;
    const int jlo = blockIdx.y * KSJ;
    const int r1 = wm * 16 + gid, r2 = r1 + 8;
    const int lrr0 = (t) >> 5,          lcc0 = ((t) & 31) << 2;
    const int lrr1 = (t + 256) >> 5,    lcc1 = ((t + 256) & 31) << 2;
    const int lrr2 = (t + 512) >> 5,    lcc2 = ((t + 512) & 31) << 2;
    const int lrr3 = (t + 768) >> 5,    lcc3 = ((t + 768) & 31) << 2;

    // ---- stage hq tile through BtW (coalesced), then hoist A-fragments ------
    {
        float4 v;
        v = *reinterpret_cast<const float4*>(g_hk2 + (size_t)(i0 + lrr0) * HH + lcc0);
        v.x=tfr(v.x); v.y=tfr(v.y); v.z=tfr(v.z); v.w=tfr(v.w);
        *reinterpret_cast<float4*>(&BtW[lrr0][lcc0]) = v;
        v = *reinterpret_cast<const float4*>(g_hk2 + (size_t)(i0 + lrr1) * HH + lcc1);
        v.x=tfr(v.x); v.y=tfr(v.y); v.z=tfr(v.z); v.w=tfr(v.w);
        *reinterpret_cast<float4*>(&BtW[lrr1][lcc1]) = v;
        v = *reinterpret_cast<const float4*>(g_hk2 + (size_t)(i0 + lrr2) * HH + lcc2);
        v.x=tfr(v.x); v.y=tfr(v.y); v.z=tfr(v.z); v.w=tfr(v.w);
        *reinterpret_cast<float4*>(&BtW[lrr2][lcc2]) = v;
        v = *reinterpret_cast<const float4*>(g_hk2 + (size_t)(i0 + lrr3) * HH + lcc3);
        v.x=tfr(v.x); v.y=tfr(v.y); v.z=tfr(v.z); v.w=tfr(v.w);
        *reinterpret_cast<float4*>(&BtW[lrr3][lcc3]) = v;
    }
    __syncthreads();
    unsigned ar1[32], ar2[32];
#pragma unroll
    for (int k = 0; k < 16; k++) {
        ar1[2*k]   = __float_as_uint(BtW[r1][8*k + tig]);
        ar1[2*k+1] = __float_as_uint(BtW[r1][8*k + 4 + tig]);
        ar2[2*k]   = __float_as_uint(BtW[r2][8*k + tig]);
        ar2[2*k+1] = __float_as_uint(BtW[r2][8*k + 4 + tig]);
    }
    __syncthreads();   // BtW free for reuse

    float cacc[4][4];
#pragma unroll
    for (int nf = 0; nf < 4; nf++)
#pragma unroll
        for (int q = 0; q < 4; q++) cacc[nf][q] = 0.f;
    float zr1 = 0.f, zr2 = 0.f;

    float4 rw0 = *reinterpret_cast<const float4*>(g_W2h + (size_t)(jlo + lrr0) * HH + lcc0);
    float4 rw1 = *reinterpret_cast<const float4*>(g_W2h + (size_t)(jlo + lrr1) * HH + lcc1);
    float4 rw2 = *reinterpret_cast<const float4*>(g_W2h + (size_t)(jlo + lrr2) * HH + lcc2);
    float4 rw3 = *reinterpret_cast<const float4*>(g_W2h + (size_t)(jlo + lrr3) * HH + lcc3);

    for (int j0 = jlo; j0 < jlo + KSJ; j0 += 32) {
        float4 rh0 = *reinterpret_cast<const float4*>(g_hk2 + (size_t)(j0 + lrr0) * HH + lcc0);
        float4 rh1 = *reinterpret_cast<const float4*>(g_hk2 + (size_t)(j0 + lrr1) * HH + lcc1);
        float4 rh2 = *reinterpret_cast<const float4*>(g_hk2 + (size_t)(j0 + lrr2) * HH + lcc2);
        float4 rh3 = *reinterpret_cast<const float4*>(g_hk2 + (size_t)(j0 + lrr3) * HH + lcc3);

        float4 v;
        v = rw0; v.x=tfr(v.x); v.y=tfr(v.y); v.z=tfr(v.z); v.w=tfr(v.w);
        *reinterpret_cast<float4*>(&BtW[lrr0][lcc0]) = v;
        v = rw1; v.x=tfr(v.x); v.y=tfr(v.y); v.z=tfr(v.z); v.w=tfr(v.w);
        *reinterpret_cast<float4*>(&BtW[lrr1][lcc1]) = v;
        v = rw2; v.x=tfr(v.x); v.y=tfr(v.y); v.z=tfr(v.z); v.w=tfr(v.w);
        *reinterpret_cast<float4*>(&BtW[lrr2][lcc2]) = v;
        v = rw3; v.x=tfr(v.x); v.y=tfr(v.y); v.z=tfr(v.z); v.w=tfr(v.w);
        *reinterpret_cast<float4*>(&BtW[lrr3][lcc3]) = v;
        v = rh0; v.x=tfr(v.x); v.y=tfr(v.y); v.z=tfr(v.z); v.w=tfr(v.w);
        *reinterpret_cast<float4*>(&Bth[lrr0][lcc0]) = v;
        v = rh1; v.x=tfr(v.x); v.y=tfr(v.y); v.z=tfr(v.z); v.w=tfr(v.w);
        *reinterpret_cast<float4*>(&Bth[lrr1][lcc1]) = v;
        v = rh2; v.x=tfr(v.x); v.y=tfr(v.y); v.z=tfr(v.z); v.w=tfr(v.w);
        *reinterpret_cast<float4*>(&Bth[lrr2][lcc2]) = v;
        v = rh3; v.x=tfr(v.x); v.y=tfr(v.y); v.z=tfr(v.z); v.w=tfr(v.w);
        *reinterpret_cast<float4*>(&Bth[lrr3][lcc3]) = v;
        __syncthreads();

        // ---- scores: A from registers, B from BtW ----
        float sc[4] = {0.f, 0.f, 0.f, 0.f};
        const int jr = wn * 8 + gid;
#pragma unroll
        for (int kss = 0; kss < 16; kss++) {
            unsigned a[4] = { ar1[2*kss], ar2[2*kss], ar1[2*kss+1], ar2[2*kss+1] };
            unsigned b[2] = { __float_as_uint(BtW[jr][kss * 8 + tig]),
                              __float_as_uint(BtW[jr][kss * 8 + tig + 4]) };
            mma_tf32(sc, a, b);
        }
        const unsigned wd1 = g_M3[(size_t)(i0 + r1) * NW + (j0 >> 5)];
        const unsigned wd2 = g_M3[(size_t)(i0 + r2) * NW + (j0 >> 5)];
        const int jl = wn * 8 + 2 * tig;
        float p0 = ((wd1 >> jl) & 1u)       ? __expf(sc[0]) : 0.f;
        float p1 = ((wd1 >> (jl + 1)) & 1u) ? __expf(sc[1]) : 0.f;
        float p2 = ((wd2 >> jl) & 1u)       ? __expf(sc[2]) : 0.f;
        float p3 = ((wd2 >> (jl + 1)) & 1u) ? __expf(sc[3]) : 0.f;
        p0 = tfr(p0); p1 = tfr(p1); p2 = tfr(p2); p3 = tfr(p3);
        zr1 += p0 + p1; zr2 += p2 + p3;
        Pst[r1][jl]     = p0;
        Pst[r1][jl + 1] = p1;
        Pst[r2][jl]     = p2;
        Pst[r2][jl + 1] = p3;
        __syncthreads();

        if (j0 + 32 < jlo + KSJ) {
            rw0 = *reinterpret_cast<const float4*>(g_W2h + (size_t)(j0 + 32 + lrr0) * HH + lcc0);
            rw1 = *reinterpret_cast<const float4*>(g_W2h + (size_t)(j0 + 32 + lrr1) * HH + lcc1);
            rw2 = *reinterpret_cast<const float4*>(g_W2h + (size_t)(j0 + 32 + lrr2) * HH + lcc2);
            rw3 = *reinterpret_cast<const float4*>(g_W2h + (size_t)(j0 + 32 + lrr3) * HH + lcc3);
        }

        // ---- PV: A from Pst, B from Bth ----
#pragma unroll
        for (int kss = 0; kss < 4; kss++) {
            unsigned a[4] = { __float_as_uint(Pst[r1][kss * 8 + tig]),
                              __float_as_uint(Pst[r2][kss * 8 + tig]),
                              __float_as_uint(Pst[r1][kss * 8 + tig + 4]),
                              __float_as_uint(Pst[r2][kss * 8 + tig + 4]) };
#pragma unroll
            for (int nf = 0; nf < 4; nf++) {
                const int ch = wn * 32 + nf * 8 + gid;
                unsigned b[2] = { __float_as_uint(Bth[kss * 8 + tig][ch]),
                                  __float_as_uint(Bth[kss * 8 + tig + 4][ch]) };
                mma_tf32(cacc[nf], a, b);
            }
        }
        __syncthreads();
    }

    zr1 += __shfl_xor_sync(0xFFFFFFFFu, zr1, 1);
    zr1 += __shfl_xor_sync(0xFFFFFFFFu, zr1, 2);
    zr2 += __shfl_xor_sync(0xFFFFFFFFu, zr2, 1);
    zr2 += __shfl_xor_sync(0xFFFFFFFFu, zr2, 2);
    if (tig == 0) { Zp[wn][r1] = zr1; Zp[wn][r2] = zr2; }
    __syncthreads();
    if (wn == 0 && tig == 0) {
        g_zp[blockIdx.y * NN + i0 + r1] = (Zp[0][r1] + Zp[1][r1]) + (Zp[2][r1] + Zp[3][r1]);
        g_zp[blockIdx.y * NN + i0 + r2] = (Zp[0][r2] + Zp[1][r2]) + (Zp[2][r2] + Zp[3][r2]);
    }
    float* P = g_hp + (size_t)blockIdx.y * NN * HH;
#pragma unroll
    for (int nf = 0; nf < 4; nf++) {
        const int ch = wn * 32 + nf * 8 + 2 * tig;
        P[(size_t)(i0 + r1) * HH + ch]     = cacc[nf][0];
        P[(size_t)(i0 + r1) * HH + ch + 1] = cacc[nf][1];
        P[(size_t)(i0 + r2) * HH + ch]     = cacc[nf][2];
        P[(size_t)(i0 + r2) * HH + ch + 1] = cacc[nf][3];
    }
}

// ---------------- final: O = O0 + O1 + dense; out = (U + O, O) ---------------
__global__ void final_kernel(const float* __restrict__ U, float* __restrict__ out) {
    const int i = blockIdx.x, t = threadIdx.x;
    const size_t ix = (size_t)i * HH + t;
    const float z = g_zp[i] + g_zp[NN + i];
    const float Od = (g_hp[ix] + g_hp[(size_t)NN * HH + ix]) / z;
    const float O  = g_O0[ix] + g_O1[ix] + Od;
    out[ix] = U[ix] + O;
    out[(size_t)NN * HH + ix] = O;
}

// ---------------- launch: mask chain + sparse hops on ONE side stream --------
extern "C" void kernel_launch(void* const* d_in, const int* in_sizes, int n_in,
                              void* d_out, int out_size) {
    const float* X  = (const float*)d_in[0];
    const float* A  = (const float*)d_in[1];
    const float* U  = (const float*)d_in[2];
    const float* W1 = (const float*)d_in[3];
    const float* W2 = (const float*)d_in[4];
    const float* r  = (const float*)d_in[5];
    float* out = (float*)d_out;

    cudaStream_t sB;
    cudaStreamCreateWithFlags(&sB, cudaStreamNonBlocking);
    cudaEvent_t e0, eS12, eM3, eJ;
    cudaEventCreateWithFlags(&e0,   cudaEventDisableTiming);
    cudaEventCreateWithFlags(&eS12, cudaEventDisableTiming);
    cudaEventCreateWithFlags(&eM3,  cudaEventDisableTiming);
    cudaEventCreateWithFlags(&eJ,   cudaEventDisableTiming);

    // fork point (side stream must first wait on a captured event)
    cudaEventRecord(e0, 0);

    // side stream: mask chain (needs only A)
    cudaStreamWaitEvent(sB, e0, 0);
    maskbuild_kernel<<<NMB, 256, 0, sB>>>(A);
    boolmm_kernel<<<NN, 128, 0, sB>>>(0);       // M2
    boolmm_kernel<<<NN, 128, 0, sB>>>(1);       // M3
    cudaEventRecord(eM3, sB);

    // main stream: prep chain (needs only X, W1, W2, r), then dense hop 2
    prep_kernel<<<NN / 32, 256>>>(X, W1, W2);
    s12_kernel<<<NN, 128>>>(r);
    cudaEventRecord(eS12, 0);                   // W1h/W2h/s1/s2 ready
    cudaStreamWaitEvent(0, eM3, 0);
    dattn1_tc<<<dim3(NN / 32, 2), 256>>>();
    combine1_kernel<<<NN, 128>>>();
    dattn2_tc<<<dim3(NN / 32, 2), 256>>>();

    // side stream continues: sparse hops (M1/M2 in-order; needs s12)
    cudaStreamWaitEvent(sB, eS12, 0);
    sattn1_kernel<<<NN, 256, 0, sB>>>(0);       // hop 0 (needs M1)
    sattn2_kernel<<<NN, 256, 0, sB>>>(0);
    sattn1_kernel<<<NN, 256, 0, sB>>>(1);       // hop 1 (needs M2)
    sattn2_kernel<<<NN, 256, 0, sB>>>(1);
    cudaEventRecord(eJ, sB);

    // join and finalize
    cudaStreamWaitEvent(0, eJ, 0);
    final_kernel<<<NN, 128>>>(U, out);
}

// round 17
// speedup vs baseline: 1.0515x; 1.0515x over previous
#include <cuda_runtime.h>

#define NN   4096
#define INF  256
#define HH   128
#define NW   128      // mask words per row
#define KSJ  2048     // j-range per K-split (split = 2)
#define NMB  (NN * NN / 256)   // maskbuild blocks
#define PR   16       // prep rows per block

// ---------------- scratch (device globals) -----------------------------------
__device__ float    g_W1h[NN * HH];
__device__ float    g_W2h[NN * HH];
__device__ float    g_s1[NN];
__device__ float    g_s2[NN];
__device__ unsigned g_M1[NN * NW];
__device__ unsigned g_M2[NN * NW];
__device__ unsigned g_M3[NN * NW];
__device__ float    g_hk0[NN * HH];
__device__ float    g_hk1[NN * HH];
__device__ float    g_hk2[NN * HH];
__device__ float    g_O0[NN * HH];
__device__ float    g_O1[NN * HH];
__device__ float    g_hp[2 * NN * HH];
__device__ float    g_zp[2 * NN];

// ---------------- tf32 helpers -----------------------------------------------
__device__ __forceinline__ float tfr(float f) {
    unsigned u;
    asm("cvt.rna.tf32.f32 %0, %1;" : "=r"(u) : "f"(f));
    return __uint_as_float(u);
}
__device__ __forceinline__ void mma_tf32(float* c, const unsigned* a, const unsigned* b) {
    asm("mma.sync.aligned.m16n8k8.row.col.f32.tf32.tf32.f32 "
        "{%0,%1,%2,%3},{%4,%5,%6,%7},{%8,%9},{%0,%1,%2,%3};"
        : "+f"(c[0]), "+f"(c[1]), "+f"(c[2]), "+f"(c[3])
        : "r"(a[0]), "r"(a[1]), "r"(a[2]), "r"(a[3]), "r"(b[0]), "r"(b[1]));
}

// ---------------- K1: W1h = X@W1^T, W2h = X@W2^T (PR rows/block) -------------
__global__ void prep_kernel(const float* __restrict__ X,
                            const float* __restrict__ W1,
                            const float* __restrict__ W2) {
    __shared__ float xs[PR][INF];
    const int t    = threadIdx.x;
    const int row0 = blockIdx.x * PR;

    const float4* Xv  = reinterpret_cast<const float4*>(X + (size_t)row0 * INF);
    float4*       xsv = reinterpret_cast<float4*>(&xs[0][0]);
    for (int k = t; k < PR * INF / 4; k += 256) xsv[k] = Xv[k];
    __syncthreads();

    const float* W = (t < HH) ? (W1 + (size_t)t * INF)
                              : (W2 + (size_t)(t - HH) * INF);
    float acc[PR];
#pragma unroll
    for (int rr = 0; rr < PR; rr++) acc[rr] = 0.f;

    for (int c = 0; c < INF; c += 4) {
        float4 w4 = *reinterpret_cast<const float4*>(W + c);
#pragma unroll
        for (int rr = 0; rr < PR; rr++) {
            float4 x4 = *reinterpret_cast<const float4*>(&xs[rr][c]);
            acc[rr] += x4.x * w4.x + x4.y * w4.y + x4.z * w4.z + x4.w * w4.w;
        }
    }
#pragma unroll
    for (int rr = 0; rr < PR; rr++) {
        const int row = row0 + rr;
        if (t < HH) g_W1h[(size_t)row * HH + t] = acc[rr];
        else        g_W2h[(size_t)row * HH + (t - HH)] = acc[rr];
    }
}

// ---------------- K2: maskbuild + s12 (heterogeneous grid) -------------------
__global__ void mask_s12_kernel(const float* __restrict__ A,
                                const float* __restrict__ r) {
    const int b = blockIdx.x, t = threadIdx.x;
    if (b < NMB) {
        const int gid = b * 256 + t;
        const float a = A[gid];
        const unsigned w = __ballot_sync(0xFFFFFFFFu, a != 0.0f);
        if ((t & 31) == 0) g_M1[gid >> 5] = w;
        return;
    }
    const int i = b - NMB;
    __shared__ float sh1[4], sh2[4];
    if (t < 128) {
        const float w  = g_W1h[(size_t)i * HH + t];
        float v1 = w * r[t];
        float v2 = w * r[HH + t];
#pragma unroll
        for (int o = 16; o; o >>= 1) {
            v1 += __shfl_xor_sync(0xFFFFFFFFu, v1, o);
            v2 += __shfl_xor_sync(0xFFFFFFFFu, v2, o);
        }
        if ((t & 31) == 0) { sh1[t >> 5] = v1; sh2[t >> 5] = v2; }
    }
    __syncthreads();
    if (t == 0) g_s1[i] = sh1[0] + sh1[1] + sh1[2] + sh1[3];
    if (t == 1) g_s2[i] = sh2[0] + sh2[1] + sh2[2] + sh2[3];
}

// ---------------- K3: boolean mat-power --------------------------------------
__global__ void boolmm_kernel(int mode) {
    const unsigned* Min  = (mode == 0) ? g_M1 : g_M2;
    unsigned*       Mout = (mode == 0) ? g_M2 : g_M3;
    const int i = blockIdx.x, t = threadIdx.x;
    __shared__ unsigned sh[NW];
    sh[t] = g_M1[(size_t)i * NW + t];
    __syncthreads();
    unsigned acc = 0;
    for (int w = 0; w < NW; w++) {
        unsigned bits = sh[w];
        while (bits) {
            const int b = __ffs(bits) - 1;
            bits &= bits - 1;
            acc |= Min[(size_t)(w * 32 + b) * NW + t];
        }
    }
    Mout[(size_t)i * NW + t] = acc;
}

// ================= SPARSE kernels (hops 0,1) =================================
__global__ __launch_bounds__(256) void sattn1_kernel(int hop) {
    const unsigned* M = (hop == 0) ? g_M1 : g_M2;
    float* hkout      = (hop == 0) ? g_hk0 : g_hk1;
    const int i = blockIdx.x;
    __shared__ unsigned short idxs[NN];
    __shared__ float plist[NN];
    __shared__ int   wsum[4];
    __shared__ float comb[HH + 4];

    const int t = threadIdx.x, l = t & 31, w = t >> 5;
    int c = 0, sc = 0; unsigned word = 0;
    if (t < 128) {
        word = M[(size_t)i * NW + t];
        c = __popc(word); sc = c;
#pragma unroll
        for (int o = 1; o < 32; o <<= 1) {
            int v = __shfl_up_sync(0xFFFFFFFFu, sc, o);
            if (l >= o) sc += v;
        }
        if (l == 31) wsum[w] = sc;
    }
    __syncthreads();
    const int n = wsum[0] + wsum[1] + wsum[2] + wsum[3];
    if (t < 128) {
        int base = 0;
#pragma unroll
        for (int q = 0; q < 4; q++) if (q < w) base += wsum[q];
        int off = base + sc - c;
        const float s1i = g_s1[i];
        unsigned b = word;
        while (b) {
            const int bit = __ffs(b) - 1;
            b &= b - 1;
            const int j = t * 32 + bit;
            const float e  = s1i + g_s2[j];
            const float lr = fmaxf(e, 0.2f * e);
            idxs[off]  = (unsigned short)j;
            plist[off] = __expf(lr - 40.0f);
            off++;
        }
    }
    __syncthreads();

    const int h = t >> 7, tl = t & 127;
    int nh = ((n >> 1) + 3) & ~3; if (nh > n) nh = n;
    const int k0 = h ? nh : 0, k1 = h ? n : nh;
    float a0 = 0.f, a1 = 0.f, a2 = 0.f, a3 = 0.f;
    float z0 = 0.f, z1 = 0.f, z2 = 0.f, z3 = 0.f;
    int k = k0;
    for (; k + 4 <= k1; k += 4) {
        const float p0 = plist[k], p1 = plist[k+1], p2 = plist[k+2], p3 = plist[k+3];
        const int j0 = idxs[k], j1 = idxs[k+1], j2 = idxs[k+2], j3 = idxs[k+3];
        a0 = fmaf(p0, g_W1h[(size_t)j0 * HH + tl], a0); z0 += p0;
        a1 = fmaf(p1, g_W1h[(size_t)j1 * HH + tl], a1); z1 += p1;
        a2 = fmaf(p2, g_W1h[(size_t)j2 * HH + tl], a2); z2 += p2;
        a3 = fmaf(p3, g_W1h[(size_t)j3 * HH + tl], a3); z3 += p3;
    }
    for (; k < k1; k++) {
        const float p = plist[k];
        a0 = fmaf(p, g_W1h[(size_t)idxs[k] * HH + tl], a0); z0 += p;
    }
    const float acc = (a0 + a1) + (a2 + a3);
    const float z   = (z0 + z1) + (z2 + z3);
    if (h == 1) { comb[tl] = acc; if (tl == 0) comb[HH] = z; }
    __syncthreads();
    if (h == 0)
        hkout[(size_t)i * HH + tl] = (acc + comb[tl]) / (z + comb[HH]);
}

__global__ __launch_bounds__(256) void sattn2_kernel(int hop) {
    const unsigned* M  = (hop == 0) ? g_M1 : g_M2;
    const float* hkin  = (hop == 0) ? g_hk0 : g_hk1;
    float* Oout        = (hop == 0) ? g_O0 : g_O1;
    const int i = blockIdx.x;
    __shared__ unsigned short idxs[NN];
    __shared__ float plist[NN];
    __shared__ int   wsum[4];
    __shared__ float comb[HH + 4];

    const int t = threadIdx.x, l = t & 31, w = t >> 5;
    const float hv0 = hkin[(size_t)i * HH + l];
    const float hv1 = hkin[(size_t)i * HH + l + 32];
    const float hv2 = hkin[(size_t)i * HH + l + 64];
    const float hv3 = hkin[(size_t)i * HH + l + 96];

    int c = 0, sc = 0; unsigned word = 0;
    if (t < 128) {
        word = M[(size_t)i * NW + t];
        c = __popc(word); sc = c;
#pragma unroll
        for (int o = 1; o < 32; o <<= 1) {
            int v = __shfl_up_sync(0xFFFFFFFFu, sc, o);
            if (l >= o) sc += v;
        }
        if (l == 31) wsum[w] = sc;
    }
    __syncthreads();
    const int n = wsum[0] + wsum[1] + wsum[2] + wsum[3];
    if (t < 128) {
        int base = 0;
#pragma unroll
        for (int q = 0; q < 4; q++) if (q < w) base += wsum[q];
        int off = base + sc - c;
        unsigned b = word;
        while (b) {
            const int bit = __ffs(b) - 1;
            b &= b - 1;
            idxs[off++] = (unsigned short)(t * 32 + bit);
        }
    }
    __syncthreads();

    int k = w;
    for (; k + 8 < n; k += 16) {
        const int ja = idxs[k], jb = idxs[k + 8];
        const float* Wa = g_W2h + (size_t)ja * HH;
        const float* Wb = g_W2h + (size_t)jb * HH;
        float da = hv0 * Wa[l] + hv1 * Wa[l+32] + hv2 * Wa[l+64] + hv3 * Wa[l+96];
        float db = hv0 * Wb[l] + hv1 * Wb[l+32] + hv2 * Wb[l+64] + hv3 * Wb[l+96];
#pragma unroll
        for (int o = 16; o; o >>= 1) {
            da += __shfl_xor_sync(0xFFFFFFFFu, da, o);
            db += __shfl_xor_sync(0xFFFFFFFFu, db, o);
        }
        if (l == 0) { plist[k] = __expf(da); plist[k + 8] = __expf(db); }
    }
    for (; k < n; k += 8) {
        const int j = idxs[k];
        const float* W = g_W2h + (size_t)j * HH;
        float d = hv0 * W[l] + hv1 * W[l+32] + hv2 * W[l+64] + hv3 * W[l+96];
#pragma unroll
        for (int o = 16; o; o >>= 1) d += __shfl_xor_sync(0xFFFFFFFFu, d, o);
        if (l == 0) plist[k] = __expf(d);
    }
    __syncthreads();

    const int h = t >> 7, tl = t & 127;
    int nh = ((n >> 1) + 3) & ~3; if (nh > n) nh = n;
    const int k0 = h ? nh : 0, k1 = h ? n : nh;
    float a0 = 0.f, a1 = 0.f, a2 = 0.f, a3 = 0.f;
    float z0 = 0.f, z1 = 0.f, z2 = 0.f, z3 = 0.f;
    k = k0;
    for (; k + 4 <= k1; k += 4) {
        const float p0 = plist[k], p1 = plist[k+1], p2 = plist[k+2], p3 = plist[k+3];
        const int j0 = idxs[k], j1 = idxs[k+1], j2 = idxs[k+2], j3 = idxs[k+3];
        a0 = fmaf(p0, hkin[(size_t)j0 * HH + tl], a0); z0 += p0;
        a1 = fmaf(p1, hkin[(size_t)j1 * HH + tl], a1); z1 += p1;
        a2 = fmaf(p2, hkin[(size_t)j2 * HH + tl], a2); z2 += p2;
        a3 = fmaf(p3, hkin[(size_t)j3 * HH + tl], a3); z3 += p3;
    }
    for (; k < k1; k++) {
        const float p = plist[k];
        a0 = fmaf(p, hkin[(size_t)idxs[k] * HH + tl], a0); z0 += p;
    }
    const float acc = (a0 + a1) + (a2 + a3);
    const float z   = (z0 + z1) + (z2 + z3);
    if (h == 1) { comb[tl] = acc; if (tl == 0) comb[HH] = z; }
    __syncthreads();
    if (h == 0)
        Oout[(size_t)i * HH + tl] = (acc + comb[tl]) / (z + comb[HH]);
}

// ================= DENSE tf32 tensor-core kernels (hop 2) ====================
__global__ __launch_bounds__(256, 2) void dattn1_tc() {
    __shared__ float s2s[NN];
    __shared__ float Vt[32][136];
    const int t = threadIdx.x, warp = t >> 5, lane = t & 31;
    const int gid = lane >> 2, tig = lane & 3;
    const int wm = warp >> 2, wn = warp & 3;
    const int i0 = blockIdx.x * 32;
    const int jlo = blockIdx.y * KSJ;
    const int r1 = wm * 16 + gid, r2 = r1 + 8;
    const int lrr0 = (t) >> 5,          lcc0 = ((t) & 31) << 2;
    const int lrr1 = (t + 256) >> 5,    lcc1 = ((t + 256) & 31) << 2;
    const int lrr2 = (t + 512) >> 5,    lcc2 = ((t + 512) & 31) << 2;
    const int lrr3 = (t + 768) >> 5,    lcc3 = ((t + 768) & 31) << 2;

    for (int k = t; k < NN / 4; k += 256)
        reinterpret_cast<float4*>(s2s)[k] = reinterpret_cast<const float4*>(g_s2)[k];

    const float s1a = g_s1[i0 + r1];
    const float s1b = g_s1[i0 + r2];

    float cacc[4][4];
#pragma unroll
    for (int nf = 0; nf < 4; nf++)
#pragma unroll
        for (int q = 0; q < 4; q++) cacc[nf][q] = 0.f;
    float zr1 = 0.f, zr2 = 0.f;

    float4 rv0 = *reinterpret_cast<const float4*>(g_W1h + (size_t)(jlo + lrr0) * HH + lcc0);
    float4 rv1 = *reinterpret_cast<const float4*>(g_W1h + (size_t)(jlo + lrr1) * HH + lcc1);
    float4 rv2 = *reinterpret_cast<const float4*>(g_W1h + (size_t)(jlo + lrr2) * HH + lcc2);
    float4 rv3 = *reinterpret_cast<const float4*>(g_W1h + (size_t)(jlo + lrr3) * HH + lcc3);
    __syncthreads();

    for (int j0 = jlo; j0 < jlo + KSJ; j0 += 32) {
        float4 v;
        v = rv0; v.x=tfr(v.x); v.y=tfr(v.y); v.z=tfr(v.z); v.w=tfr(v.w);
        *reinterpret_cast<float4*>(&Vt[lrr0][lcc0]) = v;
        v = rv1; v.x=tfr(v.x); v.y=tfr(v.y); v.z=tfr(v.z); v.w=tfr(v.w);
        *reinterpret_cast<float4*>(&Vt[lrr1][lcc1]) = v;
        v = rv2; v.x=tfr(v.x); v.y=tfr(v.y); v.z=tfr(v.z); v.w=tfr(v.w);
        *reinterpret_cast<float4*>(&Vt[lrr2][lcc2]) = v;
        v = rv3; v.x=tfr(v.x); v.y=tfr(v.y); v.z=tfr(v.z); v.w=tfr(v.w);
        *reinterpret_cast<float4*>(&Vt[lrr3][lcc3]) = v;
        __syncthreads();

        if (j0 + 32 < jlo + KSJ) {
            rv0 = *reinterpret_cast<const float4*>(g_W1h + (size_t)(j0 + 32 + lrr0) * HH + lcc0);
            rv1 = *reinterpret_cast<const float4*>(g_W1h + (size_t)(j0 + 32 + lrr1) * HH + lcc1);
            rv2 = *reinterpret_cast<const float4*>(g_W1h + (size_t)(j0 + 32 + lrr2) * HH + lcc2);
            rv3 = *reinterpret_cast<const float4*>(g_W1h + (size_t)(j0 + 32 + lrr3) * HH + lcc3);
        }

        const unsigned wd1 = g_M3[(size_t)(i0 + r1) * NW + (j0 >> 5)];
        const unsigned wd2 = g_M3[(size_t)(i0 + r2) * NW + (j0 >> 5)];
#pragma unroll
        for (int kss = 0; kss < 4; kss++) {
            const int cA = kss * 8 + tig, cB = cA + 4;
            const float s2A = s2s[j0 + cA], s2B = s2s[j0 + cB];
            const float eA1 = s1a + s2A, eA2 = s1b + s2A;
            const float eB1 = s1a + s2B, eB2 = s1b + s2B;
            float p0 = ((wd1 >> cA) & 1u) ? __expf(fmaxf(eA1, 0.2f * eA1) - 40.f) : 0.f;
            float p1 = ((wd2 >> cA) & 1u) ? __expf(fmaxf(eA2, 0.2f * eA2) - 40.f) : 0.f;
            float p2 = ((wd1 >> cB) & 1u) ? __expf(fmaxf(eB1, 0.2f * eB1) - 40.f) : 0.f;
            float p3 = ((wd2 >> cB) & 1u) ? __expf(fmaxf(eB2, 0.2f * eB2) - 40.f) : 0.f;
            p0 = tfr(p0); p1 = tfr(p1); p2 = tfr(p2); p3 = tfr(p3);
            if (wn == 0) { zr1 += p0 + p2; zr2 += p1 + p3; }
            unsigned a[4] = { __float_as_uint(p0), __float_as_uint(p1),
                              __float_as_uint(p2), __float_as_uint(p3) };
#pragma unroll
            for (int nf = 0; nf < 4; nf++) {
                const int ch = wn * 32 + nf * 8 + gid;
                unsigned b[2] = { __float_as_uint(Vt[cA][ch]),
                                  __float_as_uint(Vt[cB][ch]) };
                mma_tf32(cacc[nf], a, b);
            }
        }
        __syncthreads();
    }

    if (wn == 0) {
        zr1 += __shfl_xor_sync(0xFFFFFFFFu, zr1, 1);
        zr1 += __shfl_xor_sync(0xFFFFFFFFu, zr1, 2);
        zr2 += __shfl_xor_sync(0xFFFFFFFFu, zr2, 1);
        zr2 += __shfl_xor_sync(0xFFFFFFFFu, zr2, 2);
        if (tig == 0) {
            g_zp[blockIdx.y * NN + i0 + r1] = zr1;
            g_zp[blockIdx.y * NN + i0 + r2] = zr2;
        }
    }
    float* P = g_hp + (size_t)blockIdx.y * NN * HH;
#pragma unroll
    for (int nf = 0; nf < 4; nf++) {
        const int ch = wn * 32 + nf * 8 + 2 * tig;
        P[(size_t)(i0 + r1) * HH + ch]     = cacc[nf][0];
        P[(size_t)(i0 + r1) * HH + ch + 1] = cacc[nf][1];
        P[(size_t)(i0 + r2) * HH + ch]     = cacc[nf][2];
        P[(size_t)(i0 + r2) * HH + ch + 1] = cacc[nf][3];
    }
}

__global__ void combine1_kernel() {
    const int i = blockIdx.x, t = threadIdx.x;
    const size_t ix = (size_t)i * HH + t;
    const float z = g_zp[i] + g_zp[NN + i];
    g_hk2[ix] = (g_hp[ix] + g_hp[(size_t)NN * HH + ix]) / z;
}

// attn2: hq A-fragments hoisted into registers; separate W2h / hk tile buffers.
__global__ __launch_bounds__(256, 2) void dattn2_tc() {
    __shared__ float BtW[32][136];
    __shared__ float Bth[32][136];
    __shared__ float Pst[32][40];
    __shared__ float Zp[4][32];
    const int t = threadIdx.x, warp = t >> 5, lane = t & 31;
    const int gid = lane >> 2, tig = lane & 3;
    const int wm = warp >> 2, wn = warp & 3;
    const int i0 = blockIdx.x * 32;
    const int jlo = blockIdx.y * KSJ;
    const int r1 = wm * 16 + gid, r2 = r1 + 8;
    const int lrr0 = (t) >> 5,          lcc0 = ((t) & 31) << 2;
    const int lrr1 = (t + 256) >> 5,    lcc1 = ((t + 256) & 31) << 2;
    const int lrr2 = (t + 512) >> 5,    lcc2 = ((t + 512) & 31) << 2;
    const int lrr3 = (t + 768) >> 5,    lcc3 = ((t + 768) & 31) << 2;

    // stage hq tile through BtW (coalesced), then hoist A-fragments
    {
        float4 v;
        v = *reinterpret_cast<const float4*>(g_hk2 + (size_t)(i0 + lrr0) * HH + lcc0);
        v.x=tfr(v.x); v.y=tfr(v.y); v.z=tfr(v.z); v.w=tfr(v.w);
        *reinterpret_cast<float4*>(&BtW[lrr0][lcc0]) = v;
        v = *reinterpret_cast<const float4*>(g_hk2 + (size_t)(i0 + lrr1) * HH + lcc1);
        v.x=tfr(v.x); v.y=tfr(v.y); v.z=tfr(v.z); v.w=tfr(v.w);
        *reinterpret_cast<float4*>(&BtW[lrr1][lcc1]) = v;
        v = *reinterpret_cast<const float4*>(g_hk2 + (size_t)(i0 + lrr2) * HH + lcc2);
        v.x=tfr(v.x); v.y=tfr(v.y); v.z=tfr(v.z); v.w=tfr(v.w);
        *reinterpret_cast<float4*>(&BtW[lrr2][lcc2]) = v;
        v = *reinterpret_cast<const float4*>(g_hk2 + (size_t)(i0 + lrr3) * HH + lcc3);
        v.x=tfr(v.x); v.y=tfr(v.y); v.z=tfr(v.z); v.w=tfr(v.w);
        *reinterpret_cast<float4*>(&BtW[lrr3][lcc3]) = v;
    }
    __syncthreads();
    unsigned ar1[32], ar2[32];
#pragma unroll
    for (int k = 0; k < 16; k++) {
        ar1[2*k]   = __float_as_uint(BtW[r1][8*k + tig]);
        ar1[2*k+1] = __float_as_uint(BtW[r1][8*k + 4 + tig]);
        ar2[2*k]   = __float_as_uint(BtW[r2][8*k + tig]);
        ar2[2*k+1] = __float_as_uint(BtW[r2][8*k + 4 + tig]);
    }
    __syncthreads();

    float cacc[4][4];
#pragma unroll
    for (int nf = 0; nf < 4; nf++)
#pragma unroll
        for (int q = 0; q < 4; q++) cacc[nf][q] = 0.f;
    float zr1 = 0.f, zr2 = 0.f;

    float4 rw0 = *reinterpret_cast<const float4*>(g_W2h + (size_t)(jlo + lrr0) * HH + lcc0);
    float4 rw1 = *reinterpret_cast<const float4*>(g_W2h + (size_t)(jlo + lrr1) * HH + lcc1);
    float4 rw2 = *reinterpret_cast<const float4*>(g_W2h + (size_t)(jlo + lrr2) * HH + lcc2);
    float4 rw3 = *reinterpret_cast<const float4*>(g_W2h + (size_t)(jlo + lrr3) * HH + lcc3);

    for (int j0 = jlo; j0 < jlo + KSJ; j0 += 32) {
        float4 rh0 = *reinterpret_cast<const float4*>(g_hk2 + (size_t)(j0 + lrr0) * HH + lcc0);
        float4 rh1 = *reinterpret_cast<const float4*>(g_hk2 + (size_t)(j0 + lrr1) * HH + lcc1);
        float4 rh2 = *reinterpret_cast<const float4*>(g_hk2 + (size_t)(j0 + lrr2) * HH + lcc2);
        float4 rh3 = *reinterpret_cast<const float4*>(g_hk2 + (size_t)(j0 + lrr3) * HH + lcc3);

        float4 v;
        v = rw0; v.x=tfr(v.x); v.y=tfr(v.y); v.z=tfr(v.z); v.w=tfr(v.w);
        *reinterpret_cast<float4*>(&BtW[lrr0][lcc0]) = v;
        v = rw1; v.x=tfr(v.x); v.y=tfr(v.y); v.z=tfr(v.z); v.w=tfr(v.w);
        *reinterpret_cast<float4*>(&BtW[lrr1][lcc1]) = v;
        v = rw2; v.x=tfr(v.x); v.y=tfr(v.y); v.z=tfr(v.z); v.w=tfr(v.w);
        *reinterpret_cast<float4*>(&BtW[lrr2][lcc2]) = v;
        v = rw3; v.x=tfr(v.x); v.y=tfr(v.y); v.z=tfr(v.z); v.w=tfr(v.w);
        *reinterpret_cast<float4*>(&BtW[lrr3][lcc3]) = v;
        v = rh0; v.x=tfr(v.x); v.y=tfr(v.y); v.z=tfr(v.z); v.w=tfr(v.w);
        *reinterpret_cast<float4*>(&Bth[lrr0][lcc0]) = v;
        v = rh1; v.x=tfr(v.x); v.y=tfr(v.y); v.z=tfr(v.z); v.w=tfr(v.w);
        *reinterpret_cast<float4*>(&Bth[lrr1][lcc1]) = v;
        v = rh2; v.x=tfr(v.x); v.y=tfr(v.y); v.z=tfr(v.z); v.w=tfr(v.w);
        *reinterpret_cast<float4*>(&Bth[lrr2][lcc2]) = v;
        v = rh3; v.x=tfr(v.x); v.y=tfr(v.y); v.z=tfr(v.z); v.w=tfr(v.w);
        *reinterpret_cast<float4*>(&Bth[lrr3][lcc3]) = v;
        __syncthreads();

        float sc[4] = {0.f, 0.f, 0.f, 0.f};
        const int jr = wn * 8 + gid;
#pragma unroll
        for (int kss = 0; kss < 16; kss++) {
            unsigned a[4] = { ar1[2*kss], ar2[2*kss], ar1[2*kss+1], ar2[2*kss+1] };
            unsigned b[2] = { __float_as_uint(BtW[jr][kss * 8 + tig]),
                              __float_as_uint(BtW[jr][kss * 8 + tig + 4]) };
            mma_tf32(sc, a, b);
        }
        const unsigned wd1 = g_M3[(size_t)(i0 + r1) * NW + (j0 >> 5)];
        const unsigned wd2 = g_M3[(size_t)(i0 + r2) * NW + (j0 >> 5)];
        const int jl = wn * 8 + 2 * tig;
        float p0 = ((wd1 >> jl) & 1u)       ? __expf(sc[0]) : 0.f;
        float p1 = ((wd1 >> (jl + 1)) & 1u) ? __expf(sc[1]) : 0.f;
        float p2 = ((wd2 >> jl) & 1u)       ? __expf(sc[2]) : 0.f;
        float p3 = ((wd2 >> (jl + 1)) & 1u) ? __expf(sc[3]) : 0.f;
        p0 = tfr(p0); p1 = tfr(p1); p2 = tfr(p2); p3 = tfr(p3);
        zr1 += p0 + p1; zr2 += p2 + p3;
        Pst[r1][jl]     = p0;
        Pst[r1][jl + 1] = p1;
        Pst[r2][jl]     = p2;
        Pst[r2][jl + 1] = p3;
        __syncthreads();

        if (j0 + 32 < jlo + KSJ) {
            rw0 = *reinterpret_cast<const float4*>(g_W2h + (size_t)(j0 + 32 + lrr0) * HH + lcc0);
            rw1 = *reinterpret_cast<const float4*>(g_W2h + (size_t)(j0 + 32 + lrr1) * HH + lcc1);
            rw2 = *reinterpret_cast<const float4*>(g_W2h + (size_t)(j0 + 32 + lrr2) * HH + lcc2);
            rw3 = *reinterpret_cast<const float4*>(g_W2h + (size_t)(j0 + 32 + lrr3) * HH + lcc3);
        }

#pragma unroll
        for (int kss = 0; kss < 4; kss++) {
            unsigned a[4] = { __float_as_uint(Pst[r1][kss * 8 + tig]),
                              __float_as_uint(Pst[r2][kss * 8 + tig]),
                              __float_as_uint(Pst[r1][kss * 8 + tig + 4]),
                              __float_as_uint(Pst[r2][kss * 8 + tig + 4]) };
#pragma unroll
            for (int nf = 0; nf < 4; nf++) {
                const int ch = wn * 32 + nf * 8 + gid;
                unsigned b[2] = { __float_as_uint(Bth[kss * 8 + tig][ch]),
                                  __float_as_uint(Bth[kss * 8 + tig + 4][ch]) };
                mma_tf32(cacc[nf], a, b);
            }
        }
        __syncthreads();
    }

    zr1 += __shfl_xor_sync(0xFFFFFFFFu, zr1, 1);
    zr1 += __shfl_xor_sync(0xFFFFFFFFu, zr1, 2);
    zr2 += __shfl_xor_sync(0xFFFFFFFFu, zr2, 1);
    zr2 += __shfl_xor_sync(0xFFFFFFFFu, zr2, 2);
    if (tig == 0) { Zp[wn][r1] = zr1; Zp[wn][r2] = zr2; }
    __syncthreads();
    if (wn == 0 && tig == 0) {
        g_zp[blockIdx.y * NN + i0 + r1] = (Zp[0][r1] + Zp[1][r1]) + (Zp[2][r1] + Zp[3][r1]);
        g_zp[blockIdx.y * NN + i0 + r2] = (Zp[0][r2] + Zp[1][r2]) + (Zp[2][r2] + Zp[3][r2]);
    }
    float* P = g_hp + (size_t)blockIdx.y * NN * HH;
#pragma unroll
    for (int nf = 0; nf < 4; nf++) {
        const int ch = wn * 32 + nf * 8 + 2 * tig;
        P[(size_t)(i0 + r1) * HH + ch]     = cacc[nf][0];
        P[(size_t)(i0 + r1) * HH + ch + 1] = cacc[nf][1];
        P[(size_t)(i0 + r2) * HH + ch]     = cacc[nf][2];
        P[(size_t)(i0 + r2) * HH + ch + 1] = cacc[nf][3];
    }
}

// ---------------- final: O = O0 + O1 + dense; out = (U + O, O) ---------------
__global__ void final_kernel(const float* __restrict__ U, float* __restrict__ out) {
    const int i = blockIdx.x, t = threadIdx.x;
    const size_t ix = (size_t)i * HH + t;
    const float z = g_zp[i] + g_zp[NN + i];
    const float Od = (g_hp[ix] + g_hp[(size_t)NN * HH + ix]) / z;
    const float O  = g_O0[ix] + g_O1[ix] + Od;
    out[ix] = U[ix] + O;
    out[(size_t)NN * HH + ix] = O;
}

// ---------------- launch: R13-proven order -----------------------------------
extern "C" void kernel_launch(void* const* d_in, const int* in_sizes, int n_in,
                              void* d_out, int out_size) {
    const float* X  = (const float*)d_in[0];
    const float* A  = (const float*)d_in[1];
    const float* U  = (const float*)d_in[2];
    const float* W1 = (const float*)d_in[3];
    const float* W2 = (const float*)d_in[4];
    const float* r  = (const float*)d_in[5];
    float* out = (float*)d_out;

    cudaStream_t sB;
    cudaStreamCreateWithFlags(&sB, cudaStreamNonBlocking);
    cudaEvent_t eF, eM2, eJ;
    cudaEventCreateWithFlags(&eF,  cudaEventDisableTiming);
    cudaEventCreateWithFlags(&eM2, cudaEventDisableTiming);
    cudaEventCreateWithFlags(&eJ,  cudaEventDisableTiming);

    // main stream: prep -> masks/s12 -> boolmm chain -> dense chain
    prep_kernel<<<NN / PR, 256>>>(X, W1, W2);
    mask_s12_kernel<<<NMB + NN, 256>>>(A, r);
    cudaEventRecord(eF, 0);                    // M1, s1/s2, W1h/W2h ready
    boolmm_kernel<<<NN, 128>>>(0);             // M2
    cudaEventRecord(eM2, 0);                   // M2 ready
    boolmm_kernel<<<NN, 128>>>(1);             // M3
    dattn1_tc<<<dim3(NN / 32, 2), 256>>>();
    combine1_kernel<<<NN, 128>>>();
    dattn2_tc<<<dim3(NN / 32, 2), 256>>>();

    // side stream: sparse hops, forked from captured events
    cudaStreamWaitEvent(sB, eF, 0);
    sattn1_kernel<<<NN, 256, 0, sB>>>(0);      // hop 0 (needs M1)
    sattn2_kernel<<<NN, 256, 0, sB>>>(0);
    cudaStreamWaitEvent(sB, eM2, 0);
    sattn1_kernel<<<NN, 256, 0, sB>>>(1);      // hop 1 (needs M2)
    sattn2_kernel<<<NN, 256, 0, sB>>>(1);
    cudaEventRecord(eJ, sB);

    // join and finalize
    cudaStreamWaitEvent(0, eJ, 0);
    final_kernel<<<NN, 128>>>(U, out);
}